// round 17
// baseline (speedup 1.0000x reference)
#include <cuda_runtime.h>
#include <cuda_bf16.h>
#include <math.h>

// B=16, C=22, L=3000, D=64, D2=256, E=8, T=4, K=13
// Only output token n=0 matters -> tokens n=0..6 (conv q=0..17, x[:, :, 0..40]).
// Single persistent kernel, 256 blocks x 512 threads, 2 software grid barriers.

#define GRID 256

__device__ float g_hln[16 * 448];        // LN'd tokens [b][n=0..6][d]
__device__ float g_tp[16 * 256];         // tokens_pre [b][o]
__device__ float g_y[16 * 3 * 256];      // gated GEMV outputs [b][g][f]
__device__ int   g_arrive;               // monotonic barrier counter
__device__ int   g_depart;               // departure counter (resets state)
__device__ int   g_cntb[16];             // per-b P4 completion counters

__device__ __forceinline__ float gelu_exact(float x) {
    return 0.5f * x * (1.0f + erff(x * 0.70710678118654752f));
}

// grid barrier k (k = 1,2,...): pass when total arrivals >= k*GRID
__device__ __forceinline__ void gbar(int k) {
    __syncthreads();
    if (threadIdx.x == 0) {
        __threadfence();
        atomicAdd(&g_arrive, 1);
        while (*((volatile int*)&g_arrive) < k * GRID) __nanosleep(64);
        __threadfence();
    }
    __syncthreads();
}

__device__ __forceinline__ float bsum512(float v, float* red) {
    #pragma unroll
    for (int off = 16; off; off >>= 1) v += __shfl_xor_sync(0xffffffffu, v, off);
    int w = threadIdx.x >> 5;
    if ((threadIdx.x & 31) == 0) red[w] = v;
    __syncthreads();
    if (threadIdx.x < 32) {
        float xv = (threadIdx.x < 16) ? red[threadIdx.x] : 0.f;
        #pragma unroll
        for (int off = 8; off; off >>= 1) xv += __shfl_xor_sync(0xffffffffu, xv, off);
        if (threadIdx.x == 0) red[0] = xv;
    }
    __syncthreads();
    float r = red[0];
    __syncthreads();
    return r;
}

__global__ void __launch_bounds__(512, 2) mega(
        const float* __restrict__ x,
        const int*   __restrict__ task_ids,
        const float* __restrict__ cw,
        const float* __restrict__ cb,
        const float* __restrict__ cls,
        const float* __restrict__ tg,
        const float* __restrict__ tb,
        const float* __restrict__ w1,
        const float* __restrict__ dcb,
        const float* __restrict__ W,
        const float* __restrict__ dcompb,
        const float* __restrict__ ds_g,
        const float* __restrict__ ds_b,
        const float* __restrict__ task_embed,
        const float* __restrict__ gate_w,
        const float* __restrict__ gate_b,
        const float* __restrict__ exp_w,
        const float* __restrict__ exp_b,
        const float* __restrict__ uni_w,
        const float* __restrict__ uni_b,
        const float* __restrict__ out_g,
        const float* __restrict__ out_b,
        float* __restrict__ out)
{
    extern __shared__ __align__(16) float s_W[];   // 16384 floats: W[o] tile [c][d]
    __shared__ __align__(16) float s_w1[2048];     // [c][k]; k=7 slot = dcb[c]
    __shared__ __align__(16) float s_up[8][8][64]; // [cgrp][k][d]
    __shared__ __align__(16) float s_part[8][256];
    __shared__ __align__(16) float s_tok[256];
    __shared__ float s_xs[22][23];
    __shared__ float s_cv2[2][3][64];
    __shared__ float s_cv[3][64];
    __shared__ float s_red16[16][16];
    __shared__ float s_red[32];
    __shared__ float s_gsh[8];
    __shared__ int   s_esel;
    __shared__ float s_coef;
    __shared__ int   s_last;

    int blk = blockIdx.x, t = threadIdx.x;
    int w = t >> 5, lane = t & 31;

    // taps for the fold (all blocks; read after the W-store __syncthreads)
    for (int l = t; l < 2048; l += 512) {
        int c = l >> 3, k = l & 7;
        s_w1[l] = (k < 7) ? __ldg(w1 + c * 13 + 6 + k) : __ldg(dcb + c);
    }

    // ---- conv phase (blocks 0..95): conv1d+GELU+maxpool+token LN (+cls LN) ----
    if (blk < 96) {
        int p = blk % 6, b = blk / 6;
        int base = 6 * p - 6;
        for (int l = t; l < 506; l += 512) {
            int c = l / 23, j = l - c * 23;
            int xi = base + j;
            s_xs[c][j] = (xi >= 0) ? x[(b * 22 + c) * 3000 + xi] : 0.f;
        }
        __syncthreads();
        if (t < 384) {   // 2 channel-groups of 11 channels each
            int grp = t / 192, idx = t % 192;
            int qi = idx >> 6, d = idx & 63;
            int cs = grp * 11;
            float acc = 0.f;
            #pragma unroll
            for (int cc = 0; cc < 10; cc += 2) {
                float wv[26];
                const float* wp = cw + d * 286 + (cs + cc) * 13;
                #pragma unroll
                for (int k = 0; k < 26; k++) wv[k] = __ldg(wp + k);
                #pragma unroll
                for (int k = 0; k < 13; k++) acc += wv[k] * s_xs[cs + cc][2 * qi + k];
                #pragma unroll
                for (int k = 0; k < 13; k++) acc += wv[13 + k] * s_xs[cs + cc + 1][2 * qi + k];
            }
            {   // 11th channel
                float wv[13];
                const float* wp = cw + d * 286 + (cs + 10) * 13;
                #pragma unroll
                for (int k = 0; k < 13; k++) wv[k] = __ldg(wp + k);
                #pragma unroll
                for (int k = 0; k < 13; k++) acc += wv[k] * s_xs[cs + 10][2 * qi + k];
            }
            s_cv2[grp][qi][d] = acc;
        }
        __syncthreads();
        if (t < 192) {
            int qi = t >> 6, d = t & 63;
            s_cv[qi][d] = gelu_exact(s_cv2[0][qi][d] + s_cv2[1][qi][d] + __ldg(cb + d));
        }
        __syncthreads();
        if (t < 32) {
            float v0 = fmaxf(fmaxf(s_cv[0][t], s_cv[1][t]), s_cv[2][t]);
            float v1 = fmaxf(fmaxf(s_cv[0][t + 32], s_cv[1][t + 32]), s_cv[2][t + 32]);
            float s = v0 + v1;
            #pragma unroll
            for (int off = 16; off; off >>= 1) s += __shfl_xor_sync(0xffffffffu, s, off);
            float mean = s * (1.f / 64.f);
            float d0 = v0 - mean, d1 = v1 - mean;
            float q = d0 * d0 + d1 * d1;
            #pragma unroll
            for (int off = 16; off; off >>= 1) q += __shfl_xor_sync(0xffffffffu, q, off);
            float rstd = rsqrtf(q * (1.f / 64.f) + 1e-5f);
            float* dst = g_hln + b * 448 + (p + 1) * 64;
            dst[t]      = d0 * rstd * __ldg(tg + t)      + __ldg(tb + t);
            dst[t + 32] = d1 * rstd * __ldg(tg + t + 32) + __ldg(tb + t + 32);
        } else if (p == 0 && t < 64) {
            int l2 = t - 32;
            float v0 = __ldg(cls + l2), v1 = __ldg(cls + l2 + 32);
            float s = v0 + v1;
            #pragma unroll
            for (int off = 16; off; off >>= 1) s += __shfl_xor_sync(0xffffffffu, s, off);
            float mean = s * (1.f / 64.f);
            float d0 = v0 - mean, d1 = v1 - mean;
            float q = d0 * d0 + d1 * d1;
            #pragma unroll
            for (int off = 16; off; off >>= 1) q += __shfl_xor_sync(0xffffffffu, q, off);
            float rstd = rsqrtf(q * (1.f / 64.f) + 1e-5f);
            float* dst = g_hln + b * 448;
            dst[l2]      = d0 * rstd * __ldg(tg + l2)      + __ldg(tb + l2);
            dst[l2 + 32] = d1 * rstd * __ldg(tg + l2 + 32) + __ldg(tb + l2 + 32);
        }
    }

    // ---- fold phase A (ALL blocks): W[o] tile -> smem (float4) -> u[8] ----
    {
        int o = blk;
        const float4* src = (const float4*)(W + (long)o * 16384);
        float4 v[8];
        #pragma unroll
        for (int i = 0; i < 8; i++) v[i] = __ldg(src + t + i * 512);
        #pragma unroll
        for (int i = 0; i < 8; i++) ((float4*)s_W)[t + i * 512] = v[i];
        __syncthreads();

        int cg = t >> 6, d = t & 63, c0 = cg * 32;
        float u[8] = {0.f, 0.f, 0.f, 0.f, 0.f, 0.f, 0.f, 0.f};
        #pragma unroll
        for (int j = 0; j < 32; j++) {
            float s = s_W[(c0 + j) * 64 + d];
            const float4* wr = (const float4*)(s_w1 + (c0 + j) * 8);
            float4 wa = wr[0], wb = wr[1];
            u[0] += s * wa.x; u[1] += s * wa.y; u[2] += s * wa.z; u[3] += s * wa.w;
            u[4] += s * wb.x; u[5] += s * wb.y; u[6] += s * wb.z; u[7] += s * wb.w;
        }
        #pragma unroll
        for (int k = 0; k < 8; k++) s_up[cg][k][d] = u[k];
    }
    gbar(1);   // hln ready everywhere; s_up ready locally

    // ---- fold phase B: dot u with hln for all 16 b -> g_tp ----
    {
        int o = blk;
        int kk = t >> 6, d = t & 63;
        float uf = 0.f;
        #pragma unroll
        for (int g = 0; g < 8; g++) uf += s_up[g][kk][d];
        float tpv[16];
        if (kk < 7) {
            const float* hp = g_hln + kk * 64 + d;
            float hv[16];
            #pragma unroll
            for (int b = 0; b < 16; b++) hv[b] = __ldg(hp + b * 448);
            #pragma unroll
            for (int b = 0; b < 16; b++) tpv[b] = uf * hv[b];
        } else {
            #pragma unroll
            for (int b = 0; b < 16; b++) tpv[b] = uf;
        }
        #pragma unroll
        for (int b = 0; b < 16; b++) {
            #pragma unroll
            for (int off = 16; off; off >>= 1)
                tpv[b] += __shfl_xor_sync(0xffffffffu, tpv[b], off);
        }
        if (lane < 16) s_red16[w][lane] = tpv[lane];
        __syncthreads();
        if (t < 16) {
            float s = 0.f;
            #pragma unroll
            for (int w2 = 0; w2 < 16; w2++) s += s_red16[w2][t];
            g_tp[t * 256 + o] = s + __ldg(dcompb + o);
        }
    }
    gbar(2);   // g_tp fully written

    // ---- P4: gate + expert/universal GEMV; last block per b does output ----
    if (blk < 48) {
        int g = blk >> 4, b = blk & 15;
        float tp = (t < 256) ? g_tp[b * 256 + t] : 0.f;
        float mean = bsum512(tp, s_red) * (1.f / 256.f);
        float dv = tp - mean;
        float var = bsum512((t < 256) ? dv * dv : 0.f, s_red) * (1.f / 256.f);
        float rstd = rsqrtf(var + 1e-5f);
        if (t < 256) s_tok[t] = gelu_exact(dv * rstd * __ldg(ds_g + t) + __ldg(ds_b + t));
        __syncthreads();
        if (t < 256) {   // warps 0..7: logit per expert
            const float* te = task_embed + __ldg(task_ids + b) * 256;
            float s = 0.f;
            #pragma unroll
            for (int i = 0; i < 8; i++) {
                int o = lane + i * 32;
                s += s_tok[o] * __ldg(gate_w + o * 8 + w)
                   + __ldg(te + o) * __ldg(gate_w + (256 + o) * 8 + w);
            }
            #pragma unroll
            for (int off = 16; off; off >>= 1) s += __shfl_xor_sync(0xffffffffu, s, off);
            if (lane == 0) s_gsh[w] = s + __ldg(gate_b + w);
        }
        __syncthreads();
        if (t == 0) {
            float v1 = -1e30f; int e1 = 0;
            #pragma unroll
            for (int e = 0; e < 8; e++) if (s_gsh[e] > v1) { v1 = s_gsh[e]; e1 = e; }
            float v2 = -1e30f; int e2 = 0;
            #pragma unroll
            for (int e = 0; e < 8; e++) if (e != e1 && s_gsh[e] > v2) { v2 = s_gsh[e]; e2 = e; }
            float g1 = 1.f / (1.f + expf(v2 - v1));
            if (g == 0)      { s_esel = e1; s_coef = g1; }
            else if (g == 1) { s_esel = e2; s_coef = 1.f - g1; }
            else             { s_esel = 8;  s_coef = 1.f - g1; }  // omega = 1 - max gate
        }
        __syncthreads();
        const float* Wb = (s_esel < 8) ? exp_w + (long)s_esel * 65536 : uni_w;
        const float* Bb = (s_esel < 8) ? exp_b + s_esel * 256 : uni_b;
        int ds = t >> 6, f4 = (t & 63) * 4;
        int d0 = ds * 32;
        float4 acc = make_float4(0.f, 0.f, 0.f, 0.f);
        #pragma unroll
        for (int blk2 = 0; blk2 < 4; blk2++) {
            float4 w4[8];
            #pragma unroll
            for (int j = 0; j < 8; j++)
                w4[j] = __ldg((const float4*)(Wb + (d0 + blk2 * 8 + j) * 256 + f4));
            #pragma unroll
            for (int j = 0; j < 8; j++) {
                float tv = s_tok[d0 + blk2 * 8 + j];
                acc.x += tv * w4[j].x; acc.y += tv * w4[j].y;
                acc.z += tv * w4[j].z; acc.w += tv * w4[j].w;
            }
        }
        *(float4*)(&s_part[ds][f4]) = acc;
        __syncthreads();
        if (t < 256) {
            float s = 0.f;
            #pragma unroll
            for (int p = 0; p < 8; p++) s += s_part[p][t];
            g_y[(b * 3 + g) * 256 + t] = s_coef * gelu_exact(s + __ldg(Bb + t));
        }
        __syncthreads();

        // ---- per-b tail: last of the 3 blocks for b does combine + final LN ----
        if (t == 0) {
            __threadfence();
            s_last = (atomicAdd(&g_cntb[b], 1) == 2) ? 1 : 0;
        }
        __syncthreads();
        if (s_last) {
            __threadfence();
            float val = 0.f;
            if (t < 256) {
                const float* y = g_y + b * 3 * 256;
                val = y[t] + y[256 + t] + y[512 + t];
            }
            float m = bsum512(val, s_red) * (1.f / 256.f);
            float dv2 = val - m;
            float vv = bsum512((t < 256) ? dv2 * dv2 : 0.f, s_red) * (1.f / 256.f);
            float rs = rsqrtf(vv + 1e-5f);
            if (t < 256) out[b * 256 + t] = dv2 * rs * __ldg(out_g + t) + __ldg(out_b + t);
            __syncthreads();
            if (t == 0) { g_cntb[b] = 0; __threadfence(); }   // reset for next replay
        }
    }

    // ---- departure: last block resets barrier counters for next replay ----
    __syncthreads();
    if (t == 0) {
        __threadfence();
        if (atomicAdd(&g_depart, 1) == GRID - 1) {
            g_arrive = 0;
            g_depart = 0;
            __threadfence();
        }
    }
}

// ---------------------------------------------------------------------------
extern "C" void kernel_launch(void* const* d_in, const int* in_sizes, int n_in,
                              void* d_out, int out_size) {
    const float* x_stream   = (const float*)d_in[0];
    const int*   task_ids   = (const int*)  d_in[1];
    const float* conv_w     = (const float*)d_in[2];
    const float* conv_b     = (const float*)d_in[3];
    const float* cls_token  = (const float*)d_in[4];
    const float* tok_g      = (const float*)d_in[5];
    const float* tok_b      = (const float*)d_in[6];
    const float* ds_conv_w  = (const float*)d_in[7];
    const float* ds_conv_b  = (const float*)d_in[8];
    const float* ds_comp_w  = (const float*)d_in[9];
    const float* ds_comp_b  = (const float*)d_in[10];
    const float* ds_g       = (const float*)d_in[11];
    const float* ds_b       = (const float*)d_in[12];
    const float* task_embed = (const float*)d_in[13];
    const float* gate_w     = (const float*)d_in[14];
    const float* gate_b     = (const float*)d_in[15];
    const float* exp_w      = (const float*)d_in[16];
    const float* exp_b      = (const float*)d_in[17];
    const float* uni_w      = (const float*)d_in[18];
    const float* uni_b      = (const float*)d_in[19];
    const float* out_g      = (const float*)d_in[20];
    const float* out_b      = (const float*)d_in[21];
    float* out = (float*)d_out;

    cudaFuncSetAttribute(mega, cudaFuncAttributeMaxDynamicSharedMemorySize,
                         16384 * sizeof(float));

    mega<<<GRID, 512, 16384 * sizeof(float)>>>(
        x_stream, task_ids, conv_w, conv_b, cls_token,
        tok_g, tok_b, ds_conv_w, ds_conv_b, ds_comp_w,
        ds_comp_b, ds_g, ds_b, task_embed, gate_w, gate_b,
        exp_w, exp_b, uni_w, uni_b, out_g, out_b, out);
}